// round 16
// baseline (speedup 1.0000x reference)
#include <cuda_runtime.h>
#include <math.h>

#define BB   64
#define NCC  20
#define KK   150
#define CC   2048
#define C4   (CC/4)
#define TL   750
#define NCH  16          // column chunks of 128 floats (32 float4)
#define T_NCE 0.07f
#define EPSF  1e-7f

// ---------------- scratch (device globals; unique writer per slot) ----------------------
__device__ float4 g_S  [2][BB*C4];        // full column sums of HA/HB
__device__ float4 g_SE [2][BB*C4];        // full column sums of EB/EA
__device__ float  g_dotp[NCH][2][BB*KK];  // per-chunk partials of S_i . e_k
__device__ float  g_nrmp[NCH][2][BB*KK];  // per-chunk partials of ||e_k||^2
__device__ float  g_nce[2*BB];
__device__ float  g_cls;
__device__ float  g_rel[8][2];
__device__ float  g_actw[TL];
__device__ float  g_acts[TL];
__device__ unsigned g_ctr = 0;            // last-block counter (self-resetting each replay)

// ================= ks: ONE stream kernel, no inter-block deps ==========================
// blocks [0,2048): (i, n, cc) — phase A: H chunk (all 150 rows) -> q column sums;
//                               phase B: E chunk -> chunk dots/norms + SE column sums.
// blocks 2048: cls ; 2049..2056: rel ; 2057..2244: act
__global__ void __launch_bounds__(256) ks(
    const float* __restrict__ HA, const float* __restrict__ HB,
    const float* __restrict__ EA, const float* __restrict__ EB,
    const float* __restrict__ vs, const float* __restrict__ lab,
    const float* __restrict__ rs, const float* __restrict__ rd,
    const float* __restrict__ a0, const float* __restrict__ a2)
{
    int bx = blockIdx.x, tid = threadIdx.x;
    int w = tid >> 5, lane = tid & 31;

    if (bx < 2048) {
        __shared__ float4 red[8][32];
        int cc = bx & 15;
        int t2 = bx >> 4;            // 0..127
        int n = t2 & 63, i = t2 >> 6;
        int col = cc * 32 + lane;    // float4 column in [0,512)

        // ---- phase A: stream H chunk, accumulate column sums ----
        const float4* H = (const float4*)(i ? HB : HA) + (size_t)n * KK * C4 + col;
        float4 s = make_float4(0.f, 0.f, 0.f, 0.f);
#pragma unroll
        for (int g = 0; g < 3; ++g) {
            float4 e[6];
#pragma unroll
            for (int j = 0; j < 6; ++j)        // 6 front-batched independent LDGs
                e[j] = __ldcs(H + (size_t)((g * 6 + j) * 8 + w) * C4);
#pragma unroll
            for (int j = 0; j < 6; ++j) {
                s.x += e[j].x; s.y += e[j].y; s.z += e[j].z; s.w += e[j].w;
            }
        }
        if (w < 6) {                           // tail rows 144..149
            float4 e = __ldcs(H + (size_t)(144 + w) * C4);
            s.x += e.x; s.y += e.y; s.z += e.z; s.w += e.w;
        }
        red[w][lane] = s;
        __syncthreads();
        float4 q = make_float4(0.f, 0.f, 0.f, 0.f);
#pragma unroll
        for (int p = 0; p < 8; ++p) {
            float4 a = red[p][lane];
            q.x += a.x; q.y += a.y; q.z += a.z; q.w += a.w;
        }
        if (w == 0) g_S[i][n * C4 + col] = q;  // full column sum (unique writer)

        // ---- phase B: stream E chunk; chunk dots/norms + SE sums ----
        const float4* E = (const float4*)(i ? EA : EB) + (size_t)n * KK * C4 + col;
        float* dout = &g_dotp[cc][i][n * KK];
        float* nout = &g_nrmp[cc][i][n * KK];
        float4 sE = make_float4(0.f, 0.f, 0.f, 0.f);
#pragma unroll
        for (int g = 0; g < 3; ++g) {
            float4 e[6];
#pragma unroll
            for (int j = 0; j < 6; ++j)
                e[j] = __ldcs(E + (size_t)((g * 6 + j) * 8 + w) * C4);
#pragma unroll
            for (int j = 0; j < 6; ++j) {
                int r = (g * 6 + j) * 8 + w;
                sE.x += e[j].x; sE.y += e[j].y; sE.z += e[j].z; sE.w += e[j].w;
                float d  = q.x*e[j].x + q.y*e[j].y + q.z*e[j].z + q.w*e[j].w;
                float nn = e[j].x*e[j].x + e[j].y*e[j].y + e[j].z*e[j].z + e[j].w*e[j].w;
                for (int o = 16; o; o >>= 1) {
                    d  += __shfl_down_sync(~0u, d,  o);
                    nn += __shfl_down_sync(~0u, nn, o);
                }
                if (lane == 0) { dout[r] = d; nout[r] = nn; }
            }
        }
        if (w < 6) {
            int r = 144 + w;
            float4 e = __ldcs(E + (size_t)r * C4);
            sE.x += e.x; sE.y += e.y; sE.z += e.z; sE.w += e.w;
            float d  = q.x*e.x + q.y*e.y + q.z*e.z + q.w*e.w;
            float nn = e.x*e.x + e.y*e.y + e.z*e.z + e.w*e.w;
            for (int o = 16; o; o >>= 1) {
                d  += __shfl_down_sync(~0u, d,  o);
                nn += __shfl_down_sync(~0u, nn, o);
            }
            if (lane == 0) { dout[r] = d; nout[r] = nn; }
        }
        __syncthreads();                       // red reuse
        red[w][lane] = sE;
        __syncthreads();
        if (w == 0) {
            float4 qe = make_float4(0.f, 0.f, 0.f, 0.f);
#pragma unroll
            for (int p = 0; p < 8; ++p) {
                float4 a = red[p][lane];
                qe.x += a.x; qe.y += a.y; qe.z += a.z; qe.w += a.w;
            }
            g_SE[i][n * C4 + col] = qe;
        }
    } else if (bx == 2048) {
        // loss_cls
        __shared__ float rowsum[BB];
        __shared__ float sm[8];
        if (tid < BB) {
            float s = 0.f;
            for (int c = 0; c < NCC; ++c) s += lab[tid * NCC + c];
            rowsum[tid] = s;
        }
        __syncthreads();
        float acc = 0.f;
        for (int e = tid; e < BB * NCC; e += 256) {
            int n = e / NCC;
            float l = lab[e] / rowsum[n];
            float v = fminf(fmaxf(vs[e], EPSF), 1.f - EPSF);
            acc += l * logf(v) + (1.f - l) * log1pf(-v);
        }
        for (int o = 16; o; o >>= 1) acc += __shfl_down_sync(~0u, acc, o);
        if (lane == 0) sm[w] = acc;
        __syncthreads();
        if (tid == 0) {
            float t2 = 0.f;
            for (int x = 0; x < 8; ++x) t2 += sm[x];
            g_cls = t2;
        }
    } else if (bx <= 2056) {
        // loss_rel partials
        int blk = bx - 2049;
        __shared__ float sma[8], smb[8];
        float ss = 0.f, sd = 0.f;
        for (int e = blk * 256 + tid; e < 2 * BB * TL; e += 8 * 256) {
            float a = 1.f - rs[e]; ss += a * a;
            float b = rd[e];       sd += b * b;
        }
        for (int o = 16; o; o >>= 1) {
            ss += __shfl_down_sync(~0u, ss, o);
            sd += __shfl_down_sync(~0u, sd, o);
        }
        if (lane == 0) { sma[w] = ss; smb[w] = sd; }
        __syncthreads();
        if (tid == 0) {
            float S = 0.f, D = 0.f;
            for (int x = 0; x < 8; ++x) { S += sma[x]; D += smb[x]; }
            g_rel[blk][0] = S; g_rel[blk][1] = D;
        }
    } else {
        // loss_act: 4 time-steps per block; 64 lanes = batch
        int tg = tid >> 6;
        int b  = tid & 63;
        int hf = (tid >> 5) & 1;
        int t  = (bx - 2057) * 4 + tg;
        bool valid = t < TL;
        float a0t = valid ? a0[b * TL + t] : 0.f;
        float a2t = valid ? a2[b * TL + t] : 0.f;
        __shared__ float smq[4][2], sma2[4][2];
        float local = 0.f;
        for (int j = 0; j < 11; ++j) {
            float sq = 0.f, ab = 0.f;
            if (valid) {
                int c = t + j - 6; c = c < 0 ? 0 : (c > TL - 1 ? TL - 1 : c);
                float d0 = a0t - a0[b * TL + c]; sq = d0 * d0;
                ab = fabsf(a2t - a2[b * TL + c]);
            }
            for (int o = 16; o; o >>= 1) {
                sq += __shfl_down_sync(~0u, sq, o);
                ab += __shfl_down_sync(~0u, ab, o);
            }
            if (lane == 0) { smq[tg][hf] = sq; sma2[tg][hf] = ab; }
            __syncthreads();
            if ((tid & 63) == 0) {
                float SQ = smq[tg][0] + smq[tg][1];
                float AB = sma2[tg][0] + sma2[tg][1];
                local += expf(-0.5f * SQ) * (AB * (1.f / BB));
            }
            __syncthreads();
        }
        if ((tid & 63) == 0 && valid) g_actw[t] = local;
        float d = valid ? (a0t - a2t) * (a0t - a2t) : 0.f;
        for (int o = 16; o; o >>= 1) d += __shfl_down_sync(~0u, d, o);
        if (lane == 0) smq[tg][hf] = d;
        __syncthreads();
        if ((tid & 63) == 0 && valid) g_acts[t] = smq[tg][0] + smq[tg][1];
    }
}

// ================= k3: per-(i,n) NCE loss; last block combines everything ============
// Chunk-partial gather is warp-parallel: 10 (array, k-tile) slots over 8 warps;
// each slot = coalesced 32-wide k slice, 16 unrolled independent chunk loads (MLP=16).
__global__ void __launch_bounds__(256) k3(const float* __restrict__ att,
                                          float* __restrict__ out)
{
    int i = blockIdx.x >> 6, n = blockIdx.x & 63;
    int tid = threadIdx.x, wid = tid >> 5, lane = tid & 31;

    __shared__ float sdd[160], snn[160];
    __shared__ float sm[8][4];
    __shared__ float bc[2];

    // ---- batched gather of chunk partials into smem ----
    const size_t CSTRIDE = (size_t)2 * BB * KK;     // floats between chunk planes
    for (int r = wid; r < 10; r += 8) {
        int arr = r / 5;          // 0 = dot, 1 = nrm
        int kt  = r % 5;
        int k   = kt * 32 + lane;
        float v = 0.f;
        if (k < KK) {
            const float* base = (arr ? &g_nrmp[0][i][n * KK + k]
                                     : &g_dotp[0][i][n * KK + k]);
#pragma unroll
            for (int cc = 0; cc < NCH; ++cc)
                v += base[cc * CSTRIDE];            // 16 independent LDGs
        }
        if (arr) snn[k] = v; else sdd[k] = v;
    }

    // ---- lpos terms from full column sums (overlaps with gather) ----
    float4 S0 = g_S[i][n * C4 + tid];
    float4 S1 = g_S[i][n * C4 + 256 + tid];
    float4 E0 = g_SE[1 - i][n * C4 + tid];
    float4 E1 = g_SE[1 - i][n * C4 + 256 + tid];
    float qss  = S0.x*S0.x+S0.y*S0.y+S0.z*S0.z+S0.w*S0.w + S1.x*S1.x+S1.y*S1.y+S1.z*S1.z+S1.w*S1.w;
    float sess = E0.x*E0.x+E0.y*E0.y+E0.z*E0.z+E0.w*E0.w + E1.x*E1.x+E1.y*E1.y+E1.z*E1.z+E1.w*E1.w;
    float dse  = S0.x*E0.x+S0.y*E0.y+S0.z*E0.z+S0.w*E0.w + S1.x*E1.x+S1.y*E1.y+S1.z*E1.z+S1.w*E1.w;

    for (int o = 16; o; o >>= 1) {
        qss  += __shfl_down_sync(~0u, qss,  o);
        sess += __shfl_down_sync(~0u, sess, o);
        dse  += __shfl_down_sync(~0u, dse,  o);
    }
    if (lane == 0) { sm[wid][0] = qss; sm[wid][1] = sess; sm[wid][2] = dse; }
    __syncthreads();
    if (tid == 0) {
        float Q = 0.f, S = 0.f, D = 0.f;
        for (int w = 0; w < 8; ++w) { Q += sm[w][0]; S += sm[w][1]; D += sm[w][2]; }
        float rq = rsqrtf(Q);
        bc[0] = rq;
        bc[1] = D * rq * rsqrtf(S) * (1.f / T_NCE);    // logit0
    }
    __syncthreads();
    float rq = bc[0], logit0 = bc[1];

    float logit = -1e30f;
    if (tid == 0) logit = logit0;
    else if (tid <= 150) {
        int k = tid - 1;
        logit = att[n * 300 + i * 150 + k] * sdd[k] * rq * rsqrtf(snn[k]) * (1.f / T_NCE);
    }
    // block max
    float mx = logit;
    for (int o = 16; o; o >>= 1) mx = fmaxf(mx, __shfl_xor_sync(~0u, mx, o));
    if (lane == 0) sm[wid][0] = mx;
    __syncthreads();
    if (tid == 0) {
        float M = -1e30f;
        for (int w = 0; w < 8; ++w) M = fmaxf(M, sm[w][0]);
        bc[0] = M;
    }
    __syncthreads();
    float M = bc[0];
    float ex = (tid <= 150) ? expf(logit - M) : 0.f;
    for (int o = 16; o; o >>= 1) ex += __shfl_down_sync(~0u, ex, o);
    if (lane == 0) sm[wid][1] = ex;
    __syncthreads();
    if (tid == 0) {
        float SE = 0.f;
        for (int w = 0; w < 8; ++w) SE += sm[w][1];
        g_nce[i * 64 + n] = logf(SE) + M - logit0;     // -log_softmax[0]
    }

    // ---- last-block final combine ----
    __shared__ unsigned last;
    __threadfence();
    __syncthreads();
    if (tid == 0) last = (atomicAdd(&g_ctr, 1u) == (unsigned)(gridDim.x - 1)) ? 1u : 0u;
    __syncthreads();
    if (!last) return;
    __threadfence();   // acquire: see all blocks' g_nce writes

    float sn2 = 0.f, sw = 0.f, ss = 0.f, sr = 0.f;
    for (int e = tid; e < 2 * BB; e += 256) sn2 += g_nce[e];
    for (int e = tid; e < TL; e += 256) { sw += g_actw[e]; ss += g_acts[e]; }
    if (tid < 16) sr = g_rel[tid >> 1][tid & 1];
    for (int o = 16; o; o >>= 1) {
        sn2 += __shfl_down_sync(~0u, sn2, o);
        sw  += __shfl_down_sync(~0u, sw,  o);
        ss  += __shfl_down_sync(~0u, ss,  o);
        sr  += __shfl_down_sync(~0u, sr,  o);
    }
    if (lane == 0) { sm[wid][0]=sn2; sm[wid][1]=sw; sm[wid][2]=ss; sm[wid][3]=sr; }
    __syncthreads();
    if (tid == 0) {
        float SN=0.f, SW=0.f, SS=0.f, SR=0.f;
        for (int w = 0; w < 8; ++w) { SN+=sm[w][0]; SW+=sm[w][1]; SS+=sm[w][2]; SR+=sm[w][3]; }
        float cls   = -g_cls * (1.f / (BB * NCC));
        float rel   = SR * (1.f / (2 * BB * TL));
        float act   = SW + 0.1f * SS * (1.f / BB);     // E_THETA=0.1, E_ALPHA=1
        float snico = SN * (1.f / BB);
        out[0] = cls + 0.01f * snico + act + 0.1f * rel;
        out[1] = cls; out[2] = snico; out[3] = act; out[4] = rel;
        g_ctr = 0;                                     // reset for next graph replay
    }
}

extern "C" void kernel_launch(void* const* d_in, const int* in_sizes, int n_in,
                              void* d_out, int out_size) {
    const float* video = (const float*)d_in[0];
    const float* label = (const float*)d_in[1];
    const float* HA    = (const float*)d_in[2];
    const float* EA    = (const float*)d_in[3];
    const float* HB    = (const float*)d_in[4];
    const float* EB    = (const float*)d_in[5];
    const float* rs    = (const float*)d_in[6];
    const float* rd    = (const float*)d_in[7];
    const float* a0    = (const float*)d_in[8];
    const float* a2    = (const float*)d_in[9];
    const float* att   = (const float*)d_in[10];
    float* out = (float*)d_out;

    ks<<<2057 + 188, 256>>>(HA, HB, EA, EB, video, label, rs, rd, a0, a2);
    k3<<<128, 256>>>(att, out);
    (void)in_sizes; (void)n_in; (void)out_size;
}

// round 17
// speedup vs baseline: 1.0314x; 1.0314x over previous
#include <cuda_runtime.h>
#include <math.h>

#define BB   64
#define NCC  20
#define KK   150
#define CC   2048
#define C4   (CC/4)
#define TL   750
#define T_NCE 0.07f
#define EPSF  1e-7f

// ---------------- scratch (device globals) ----------------------------------------------
// g_dot/g_nrm are atomic accumulators: zero-initialized at load; k3 re-zeroes the slice it
// consumed, so every graph replay starts from zero (kernels are stream-ordered).
__device__ float4 g_S  [2][BB*C4];        // full column sums of HA/HB
__device__ float4 g_SE [2][BB*C4];        // full column sums of EB/EA
__device__ float  g_dot[2][BB*KK];        // S_i . e_k   (atomicAdd from 16 chunk blocks)
__device__ float  g_nrm[2][BB*KK];        // ||e_k||^2   (atomicAdd from 16 chunk blocks)
__device__ float  g_nce[2*BB];
__device__ float  g_cls;
__device__ float  g_rel[8][2];
__device__ float  g_actw[TL];
__device__ float  g_acts[TL];
__device__ unsigned g_ctr = 0;            // last-block counter (self-resetting each replay)

// ================= ks: ONE stream kernel, no inter-block deps ==========================
// blocks [0,2048): (i, n, cc) — phase A: H chunk (all 150 rows) -> q column sums;
//                               phase B: E chunk -> dots/norms (atomic) + SE column sums.
// blocks 2048: cls ; 2049..2056: rel ; 2057..2244: act
__global__ void __launch_bounds__(256) ks(
    const float* __restrict__ HA, const float* __restrict__ HB,
    const float* __restrict__ EA, const float* __restrict__ EB,
    const float* __restrict__ vs, const float* __restrict__ lab,
    const float* __restrict__ rs, const float* __restrict__ rd,
    const float* __restrict__ a0, const float* __restrict__ a2)
{
    int bx = blockIdx.x, tid = threadIdx.x;
    int w = tid >> 5, lane = tid & 31;

    if (bx < 2048) {
        __shared__ float4 red[8][32];
        int cc = bx & 15;
        int t2 = bx >> 4;            // 0..127
        int n = t2 & 63, i = t2 >> 6;
        int col = cc * 32 + lane;    // float4 column in [0,512)

        // ---- phase A: stream H chunk, accumulate column sums ----
        const float4* H = (const float4*)(i ? HB : HA) + (size_t)n * KK * C4 + col;
        float4 s = make_float4(0.f, 0.f, 0.f, 0.f);
#pragma unroll
        for (int g = 0; g < 3; ++g) {
            float4 e[6];
#pragma unroll
            for (int j = 0; j < 6; ++j)        // 6 front-batched independent LDGs
                e[j] = __ldcs(H + (size_t)((g * 6 + j) * 8 + w) * C4);
#pragma unroll
            for (int j = 0; j < 6; ++j) {
                s.x += e[j].x; s.y += e[j].y; s.z += e[j].z; s.w += e[j].w;
            }
        }
        if (w < 6) {                           // tail rows 144..149
            float4 e = __ldcs(H + (size_t)(144 + w) * C4);
            s.x += e.x; s.y += e.y; s.z += e.z; s.w += e.w;
        }
        red[w][lane] = s;
        __syncthreads();
        float4 q = make_float4(0.f, 0.f, 0.f, 0.f);
#pragma unroll
        for (int p = 0; p < 8; ++p) {
            float4 a = red[p][lane];
            q.x += a.x; q.y += a.y; q.z += a.z; q.w += a.w;
        }
        if (w == 0) g_S[i][n * C4 + col] = q;  // full column sum (unique writer)

        // ---- phase B: stream E chunk; atomic dots/norms + SE sums ----
        const float4* E = (const float4*)(i ? EA : EB) + (size_t)n * KK * C4 + col;
        float* dout = &g_dot[i][n * KK];
        float* nout = &g_nrm[i][n * KK];
        float4 sE = make_float4(0.f, 0.f, 0.f, 0.f);
#pragma unroll
        for (int g = 0; g < 3; ++g) {
            float4 e[6];
#pragma unroll
            for (int j = 0; j < 6; ++j)
                e[j] = __ldcs(E + (size_t)((g * 6 + j) * 8 + w) * C4);
#pragma unroll
            for (int j = 0; j < 6; ++j) {
                int r = (g * 6 + j) * 8 + w;
                sE.x += e[j].x; sE.y += e[j].y; sE.z += e[j].z; sE.w += e[j].w;
                float d  = q.x*e[j].x + q.y*e[j].y + q.z*e[j].z + q.w*e[j].w;
                float nn = e[j].x*e[j].x + e[j].y*e[j].y + e[j].z*e[j].z + e[j].w*e[j].w;
                for (int o = 16; o; o >>= 1) {
                    d  += __shfl_down_sync(~0u, d,  o);
                    nn += __shfl_down_sync(~0u, nn, o);
                }
                if (lane == 0) { atomicAdd(dout + r, d); atomicAdd(nout + r, nn); }
            }
        }
        if (w < 6) {
            int r = 144 + w;
            float4 e = __ldcs(E + (size_t)r * C4);
            sE.x += e.x; sE.y += e.y; sE.z += e.z; sE.w += e.w;
            float d  = q.x*e.x + q.y*e.y + q.z*e.z + q.w*e.w;
            float nn = e.x*e.x + e.y*e.y + e.z*e.z + e.w*e.w;
            for (int o = 16; o; o >>= 1) {
                d  += __shfl_down_sync(~0u, d,  o);
                nn += __shfl_down_sync(~0u, nn, o);
            }
            if (lane == 0) { atomicAdd(dout + r, d); atomicAdd(nout + r, nn); }
        }
        __syncthreads();                       // red reuse
        red[w][lane] = sE;
        __syncthreads();
        if (w == 0) {
            float4 qe = make_float4(0.f, 0.f, 0.f, 0.f);
#pragma unroll
            for (int p = 0; p < 8; ++p) {
                float4 a = red[p][lane];
                qe.x += a.x; qe.y += a.y; qe.z += a.z; qe.w += a.w;
            }
            g_SE[i][n * C4 + col] = qe;
        }
    } else if (bx == 2048) {
        // loss_cls
        __shared__ float rowsum[BB];
        __shared__ float sm[8];
        if (tid < BB) {
            float s = 0.f;
            for (int c = 0; c < NCC; ++c) s += lab[tid * NCC + c];
            rowsum[tid] = s;
        }
        __syncthreads();
        float acc = 0.f;
        for (int e = tid; e < BB * NCC; e += 256) {
            int n = e / NCC;
            float l = lab[e] / rowsum[n];
            float v = fminf(fmaxf(vs[e], EPSF), 1.f - EPSF);
            acc += l * logf(v) + (1.f - l) * log1pf(-v);
        }
        for (int o = 16; o; o >>= 1) acc += __shfl_down_sync(~0u, acc, o);
        if (lane == 0) sm[w] = acc;
        __syncthreads();
        if (tid == 0) {
            float t2 = 0.f;
            for (int x = 0; x < 8; ++x) t2 += sm[x];
            g_cls = t2;
        }
    } else if (bx <= 2056) {
        // loss_rel partials
        int blk = bx - 2049;
        __shared__ float sma[8], smb[8];
        float ss = 0.f, sd = 0.f;
        for (int e = blk * 256 + tid; e < 2 * BB * TL; e += 8 * 256) {
            float a = 1.f - rs[e]; ss += a * a;
            float b = rd[e];       sd += b * b;
        }
        for (int o = 16; o; o >>= 1) {
            ss += __shfl_down_sync(~0u, ss, o);
            sd += __shfl_down_sync(~0u, sd, o);
        }
        if (lane == 0) { sma[w] = ss; smb[w] = sd; }
        __syncthreads();
        if (tid == 0) {
            float S = 0.f, D = 0.f;
            for (int x = 0; x < 8; ++x) { S += sma[x]; D += smb[x]; }
            g_rel[blk][0] = S; g_rel[blk][1] = D;
        }
    } else {
        // loss_act: 4 time-steps per block; 64 lanes = batch
        int tg = tid >> 6;
        int b  = tid & 63;
        int hf = (tid >> 5) & 1;
        int t  = (bx - 2057) * 4 + tg;
        bool valid = t < TL;
        float a0t = valid ? a0[b * TL + t] : 0.f;
        float a2t = valid ? a2[b * TL + t] : 0.f;
        __shared__ float smq[4][2], sma2[4][2];
        float local = 0.f;
        for (int j = 0; j < 11; ++j) {
            float sq = 0.f, ab = 0.f;
            if (valid) {
                int c = t + j - 6; c = c < 0 ? 0 : (c > TL - 1 ? TL - 1 : c);
                float d0 = a0t - a0[b * TL + c]; sq = d0 * d0;
                ab = fabsf(a2t - a2[b * TL + c]);
            }
            for (int o = 16; o; o >>= 1) {
                sq += __shfl_down_sync(~0u, sq, o);
                ab += __shfl_down_sync(~0u, ab, o);
            }
            if (lane == 0) { smq[tg][hf] = sq; sma2[tg][hf] = ab; }
            __syncthreads();
            if ((tid & 63) == 0) {
                float SQ = smq[tg][0] + smq[tg][1];
                float AB = sma2[tg][0] + sma2[tg][1];
                local += expf(-0.5f * SQ) * (AB * (1.f / BB));
            }
            __syncthreads();
        }
        if ((tid & 63) == 0 && valid) g_actw[t] = local;
        float d = valid ? (a0t - a2t) * (a0t - a2t) : 0.f;
        for (int o = 16; o; o >>= 1) d += __shfl_down_sync(~0u, d, o);
        if (lane == 0) smq[tg][hf] = d;
        __syncthreads();
        if ((tid & 63) == 0 && valid) g_acts[t] = smq[tg][0] + smq[tg][1];
    }
}

// ================= k3: per-(i,n) NCE loss; last block combines everything ============
// Reads its 300-float dot/nrm slice (2 coalesced loads/thread), then ZEROES it so the
// next graph replay's atomicAdds start from zero.
__global__ void __launch_bounds__(256) k3(const float* __restrict__ att,
                                          float* __restrict__ out)
{
    int i = blockIdx.x >> 6, n = blockIdx.x & 63;
    int tid = threadIdx.x, wid = tid >> 5, lane = tid & 31;

    __shared__ float sdd[160], snn[160];
    __shared__ float sm[8][4];
    __shared__ float bc[2];

    if (tid < KK) {
        sdd[tid] = g_dot[i][n * KK + tid];
        snn[tid] = g_nrm[i][n * KK + tid];
        g_dot[i][n * KK + tid] = 0.f;          // reset for next replay
        g_nrm[i][n * KK + tid] = 0.f;
    }

    // ---- lpos terms from full column sums (overlaps with slice load) ----
    float4 S0 = g_S[i][n * C4 + tid];
    float4 S1 = g_S[i][n * C4 + 256 + tid];
    float4 E0 = g_SE[1 - i][n * C4 + tid];
    float4 E1 = g_SE[1 - i][n * C4 + 256 + tid];
    float qss  = S0.x*S0.x+S0.y*S0.y+S0.z*S0.z+S0.w*S0.w + S1.x*S1.x+S1.y*S1.y+S1.z*S1.z+S1.w*S1.w;
    float sess = E0.x*E0.x+E0.y*E0.y+E0.z*E0.z+E0.w*E0.w + E1.x*E1.x+E1.y*E1.y+E1.z*E1.z+E1.w*E1.w;
    float dse  = S0.x*E0.x+S0.y*E0.y+S0.z*E0.z+S0.w*E0.w + S1.x*E1.x+S1.y*E1.y+S1.z*E1.z+S1.w*E1.w;

    for (int o = 16; o; o >>= 1) {
        qss  += __shfl_down_sync(~0u, qss,  o);
        sess += __shfl_down_sync(~0u, sess, o);
        dse  += __shfl_down_sync(~0u, dse,  o);
    }
    if (lane == 0) { sm[wid][0] = qss; sm[wid][1] = sess; sm[wid][2] = dse; }
    __syncthreads();
    if (tid == 0) {
        float Q = 0.f, S = 0.f, D = 0.f;
        for (int w = 0; w < 8; ++w) { Q += sm[w][0]; S += sm[w][1]; D += sm[w][2]; }
        float rq = rsqrtf(Q);
        bc[0] = rq;
        bc[1] = D * rq * rsqrtf(S) * (1.f / T_NCE);    // logit0
    }
    __syncthreads();
    float rq = bc[0], logit0 = bc[1];

    float logit = -1e30f;
    if (tid == 0) logit = logit0;
    else if (tid <= 150) {
        int k = tid - 1;
        logit = att[n * 300 + i * 150 + k] * sdd[k] * rq * rsqrtf(snn[k]) * (1.f / T_NCE);
    }
    // block max
    float mx = logit;
    for (int o = 16; o; o >>= 1) mx = fmaxf(mx, __shfl_xor_sync(~0u, mx, o));
    if (lane == 0) sm[wid][0] = mx;
    __syncthreads();
    if (tid == 0) {
        float M = -1e30f;
        for (int w = 0; w < 8; ++w) M = fmaxf(M, sm[w][0]);
        bc[0] = M;
    }
    __syncthreads();
    float M = bc[0];
    float ex = (tid <= 150) ? expf(logit - M) : 0.f;
    for (int o = 16; o; o >>= 1) ex += __shfl_down_sync(~0u, ex, o);
    if (lane == 0) sm[wid][1] = ex;
    __syncthreads();
    if (tid == 0) {
        float SE = 0.f;
        for (int w = 0; w < 8; ++w) SE += sm[w][1];
        g_nce[i * 64 + n] = logf(SE) + M - logit0;     // -log_softmax[0]
    }

    // ---- last-block final combine ----
    __shared__ unsigned last;
    __threadfence();
    __syncthreads();
    if (tid == 0) last = (atomicAdd(&g_ctr, 1u) == (unsigned)(gridDim.x - 1)) ? 1u : 0u;
    __syncthreads();
    if (!last) return;
    __threadfence();   // acquire: see all blocks' g_nce writes

    float sn2 = 0.f, sw = 0.f, ss = 0.f, sr = 0.f;
    for (int e = tid; e < 2 * BB; e += 256) sn2 += g_nce[e];
    for (int e = tid; e < TL; e += 256) { sw += g_actw[e]; ss += g_acts[e]; }
    if (tid < 16) sr = g_rel[tid >> 1][tid & 1];
    for (int o = 16; o; o >>= 1) {
        sn2 += __shfl_down_sync(~0u, sn2, o);
        sw  += __shfl_down_sync(~0u, sw,  o);
        ss  += __shfl_down_sync(~0u, ss,  o);
        sr  += __shfl_down_sync(~0u, sr,  o);
    }
    if (lane == 0) { sm[wid][0]=sn2; sm[wid][1]=sw; sm[wid][2]=ss; sm[wid][3]=sr; }
    __syncthreads();
    if (tid == 0) {
        float SN=0.f, SW=0.f, SS=0.f, SR=0.f;
        for (int w = 0; w < 8; ++w) { SN+=sm[w][0]; SW+=sm[w][1]; SS+=sm[w][2]; SR+=sm[w][3]; }
        float cls   = -g_cls * (1.f / (BB * NCC));
        float rel   = SR * (1.f / (2 * BB * TL));
        float act   = SW + 0.1f * SS * (1.f / BB);     // E_THETA=0.1, E_ALPHA=1
        float snico = SN * (1.f / BB);
        out[0] = cls + 0.01f * snico + act + 0.1f * rel;
        out[1] = cls; out[2] = snico; out[3] = act; out[4] = rel;
        g_ctr = 0;                                     // reset for next graph replay
    }
}

extern "C" void kernel_launch(void* const* d_in, const int* in_sizes, int n_in,
                              void* d_out, int out_size) {
    const float* video = (const float*)d_in[0];
    const float* label = (const float*)d_in[1];
    const float* HA    = (const float*)d_in[2];
    const float* EA    = (const float*)d_in[3];
    const float* HB    = (const float*)d_in[4];
    const float* EB    = (const float*)d_in[5];
    const float* rs    = (const float*)d_in[6];
    const float* rd    = (const float*)d_in[7];
    const float* a0    = (const float*)d_in[8];
    const float* a2    = (const float*)d_in[9];
    const float* att   = (const float*)d_in[10];
    float* out = (float*)d_out;

    ks<<<2057 + 188, 256>>>(HA, HB, EA, EB, video, label, rs, rd, a0, a2);
    k3<<<128, 256>>>(att, out);
    (void)in_sizes; (void)n_in; (void)out_size;
}